// round 6
// baseline (speedup 1.0000x reference)
#include <cuda_runtime.h>
#include <cuda_bf16.h>

// SparseAttention (entmax-1.5), GB300 sm_103a. Round 5:
//  - 2 CTAs/SM: BM=64, BN=64, 256 threads, 104KB smem -> grid 256, occupancy 2.
//  - ONE __syncthreads per K-tile (wait -> sync -> issue -> consume); collect
//    uses running shared row-max (superset-safe, zero-weight extras).
//  - warp-per-row coalesced fp32 rescore + thread-per-row bisection tail.

#define BATCH 8
#define SEQ   2048
#define DIM   128
#define BM    64
#define BN    64
#define NT    (SEQ / BN)       // 32
#define QT    (SEQ / BM)       // 32
#define CAP   64
#define CSTR  65
#define QSTR  136              // bf16 row stride (128+8): 16B aligned, ldsm conflict-free
#define NITER 100
#define STAGES 3
#define NTHREADS 256

#define TILE_B  (BN * QSTR * 2)                       // 17408 bytes per bf16 tile
#define OFF_QHI  0
#define OFF_KHI  (OFF_QHI + TILE_B)                   // 17408
#define OFF_CS   (OFF_KHI + STAGES * TILE_B)          // 69632
#define OFF_CC   (OFF_CS + BM * CSTR * 4)             // 86272
#define OFF_RM   (OFF_CC + BM * CSTR * 4)             // 102912
#define OFF_CNT  (OFF_RM + BM * 4)                    // 103168
#define OFF_TAU  (OFF_CNT + BM * 4)                   // 103424
#define OFF_Z    (OFF_TAU + BM * 4)                   // 103680
#define SMEM_BYTES (OFF_Z + BM * 4)                   // 103936 -> 2 CTAs/SM

__device__ __nv_bfloat16 g_Qh[BATCH * SEQ * DIM];
__device__ __nv_bfloat16 g_Kh[BATCH * SEQ * DIM];

__global__ void cvt_kernel(const float* __restrict__ Q, const float* __restrict__ K) {
    size_t i = ((size_t)blockIdx.x * blockDim.x + threadIdx.x) * 4;
    float4 q = *(const float4*)(Q + i);
    float4 k = *(const float4*)(K + i);
    __nv_bfloat162 q0, q1, k0, k1;
    q0.x = __float2bfloat16(q.x); q0.y = __float2bfloat16(q.y);
    q1.x = __float2bfloat16(q.z); q1.y = __float2bfloat16(q.w);
    k0.x = __float2bfloat16(k.x); k0.y = __float2bfloat16(k.y);
    k1.x = __float2bfloat16(k.z); k1.y = __float2bfloat16(k.w);
    *(__nv_bfloat162*)(g_Qh + i)     = q0;
    *(__nv_bfloat162*)(g_Qh + i + 2) = q1;
    *(__nv_bfloat162*)(g_Kh + i)     = k0;
    *(__nv_bfloat162*)(g_Kh + i + 2) = k1;
}

static __device__ __forceinline__ unsigned fenc(float f) {
    unsigned u = __float_as_uint(f);
    return (u & 0x80000000u) ? ~u : (u | 0x80000000u);
}
static __device__ __forceinline__ float fdec(unsigned e) {
    return (e & 0x80000000u) ? __uint_as_float(e & 0x7fffffffu)
                             : __uint_as_float(~e);
}
static __device__ __forceinline__ void cpasync16(unsigned dst, const void* src) {
    asm volatile("cp.async.cg.shared.global [%0], [%1], 16;\n" :: "r"(dst), "l"(src));
}
static __device__ __forceinline__ void cp_commit() {
    asm volatile("cp.async.commit_group;\n");
}
template <int N>
static __device__ __forceinline__ void cp_wait() {
    asm volatile("cp.async.wait_group %0;\n" :: "n"(N));
}
static __device__ __forceinline__ void ldsm4(unsigned* r, unsigned addr) {
    asm volatile("ldmatrix.sync.aligned.m8n8.x4.shared.b16 {%0,%1,%2,%3}, [%4];\n"
                 : "=r"(r[0]), "=r"(r[1]), "=r"(r[2]), "=r"(r[3])
                 : "r"(addr) : "memory");
}
static __device__ __forceinline__ void mma16816(float* c, const unsigned* a, const unsigned* b) {
    asm volatile("mma.sync.aligned.m16n8k16.row.col.f32.bf16.bf16.f32 "
                 "{%0,%1,%2,%3}, {%4,%5,%6,%7}, {%8,%9}, {%0,%1,%2,%3};\n"
                 : "+f"(c[0]), "+f"(c[1]), "+f"(c[2]), "+f"(c[3])
                 : "r"(a[0]), "r"(a[1]), "r"(a[2]), "r"(a[3]),
                   "r"(b[0]), "r"(b[1]));
}

__global__ __launch_bounds__(NTHREADS, 2)
void entmax_attn_kernel(const float* __restrict__ Q, const float* __restrict__ K,
                        const float* __restrict__ V, float* __restrict__ O)
{
    extern __shared__ unsigned char smem[];
    float*    candS = (float*)(smem + OFF_CS);
    int*      candC = (int*)(smem + OFF_CC);
    unsigned* rowM  = (unsigned*)(smem + OFF_RM);
    int*      cnt   = (int*)(smem + OFF_CNT);
    float*    tauA  = (float*)(smem + OFF_TAU);
    float*    zA    = (float*)(smem + OFF_Z);

    const int tid  = threadIdx.x;
    const int lane = tid & 31;
    const int wid  = tid >> 5;
    const int b    = blockIdx.y;
    const int q0   = blockIdx.x * BM;

    const float* Qb = Q + ((size_t)b * SEQ + q0) * DIM;
    const float* Kb = K + (size_t)b * SEQ * DIM;
    const float* Vb = V + (size_t)b * SEQ * DIM;
    const __nv_bfloat16* Qhb = g_Qh + ((size_t)b * SEQ + q0) * DIM;
    const __nv_bfloat16* Khb = g_Kh + (size_t)b * SEQ * DIM;

    const unsigned smemB = (unsigned)__cvta_generic_to_shared(smem);
    const unsigned qS = smemB + OFF_QHI;

    // 2x4 warp grid: warp tile 32(M) x 16(N)
    const int wm = wid & 1;          // 2 warps in M (32 rows)
    const int wn = wid >> 1;         // 4 warps in N (16 cols)
    const int g  = lane >> 2;
    const int t  = lane & 3;

    const int aRow = (lane & 7) + ((lane >> 3) & 1) * 8;  // ldsm x4 (A)
    const int aK   = ((lane >> 4) & 1) * 8;
    const int bGrp  = lane >> 3;                          // ldsm x4 (B): n16 x k16
    const int bRow4 = ((bGrp >> 1) & 1) * 8 + (lane & 7);
    const int bK4   = (bGrp & 1) * 8;

    if (tid < BM) { rowM[tid] = 0u; cnt[tid] = 0; }

    // fill mapping: 64 rows x 16 chunks(16B) = 1024 chunks, 4 per thread
    const int frow0 = tid >> 4;        // 0..15
    const int fc16  = tid & 15;

    #pragma unroll
    for (int k = 0; k < 4; k++) {      // Q tile
        int r = frow0 + k * 16;
        cpasync16(qS + r * (QSTR * 2) + fc16 * 16, Qhb + r * DIM + fc16 * 8);
    }
    {                                   // K tile 0
        unsigned kD = smemB + OFF_KHI;
        #pragma unroll
        for (int k = 0; k < 4; k++) {
            int r = frow0 + k * 16;
            cpasync16(kD + r * (QSTR * 2) + fc16 * 16, Khb + r * DIM + fc16 * 8);
        }
    }
    cp_commit();
    {                                   // K tile 1
        const __nv_bfloat16* Kt = Khb + (size_t)BN * DIM;
        unsigned kD = smemB + OFF_KHI + TILE_B;
        #pragma unroll
        for (int k = 0; k < 4; k++) {
            int r = frow0 + k * 16;
            cpasync16(kD + r * (QSTR * 2) + fc16 * 16, Kt + r * DIM + fc16 * 8);
        }
    }
    cp_commit();

    for (int nt = 0; nt < NT; nt++) {
        // tile nt resident for *this thread's* copies
        if (nt < NT - 1) cp_wait<1>(); else cp_wait<0>();
        // all threads' copies of tile nt visible; all warps done reading nt-1
        __syncthreads();
        // prefetch nt+2 into the stage tile nt-1 just vacated
        if (nt + 2 < NT) {
            const __nv_bfloat16* Kt = Khb + (size_t)(nt + 2) * BN * DIM;
            unsigned kD = smemB + OFF_KHI + ((nt + 2) % STAGES) * TILE_B;
            #pragma unroll
            for (int k = 0; k < 4; k++) {
                int r = frow0 + k * 16;
                cpasync16(kD + r * (QSTR * 2) + fc16 * 16, Kt + r * DIM + fc16 * 8);
            }
            cp_commit();
        }

        const unsigned kS = smemB + OFF_KHI + (nt % STAGES) * TILE_B;

        float acc[2][2][4];
        #pragma unroll
        for (int m = 0; m < 2; m++)
            #pragma unroll
            for (int n = 0; n < 2; n++)
                #pragma unroll
                for (int e = 0; e < 4; e++) acc[m][n][e] = 0.f;

        #pragma unroll
        for (int ks = 0; ks < 8; ks++) {
            unsigned a[2][4], bb[4];
            #pragma unroll
            for (int m = 0; m < 2; m++)
                ldsm4(a[m], qS + (unsigned)(((wm * 32 + m * 16 + aRow) * QSTR + ks * 16 + aK) * 2));
            ldsm4(bb, kS + (unsigned)(((wn * 16 + bRow4) * QSTR + ks * 16 + bK4) * 2));
            #pragma unroll
            for (int m = 0; m < 2; m++) {
                mma16816(acc[m][0], a[m], &bb[0]);
                mma16816(acc[m][1], a[m], &bb[2]);
            }
        }

        // per-row running max (encoded atomicMax); no block barrier needed:
        // threshold read below includes at least this warp's contribution.
        #pragma unroll
        for (int m = 0; m < 2; m++) {
            #pragma unroll
            for (int h = 0; h < 2; h++) {
                float lm = -3.0e38f;
                #pragma unroll
                for (int n = 0; n < 2; n++)
                    lm = fmaxf(lm, fmaxf(acc[m][n][h * 2], acc[m][n][h * 2 + 1]));
                lm = fmaxf(lm, __shfl_xor_sync(0xffffffffu, lm, 1));
                lm = fmaxf(lm, __shfl_xor_sync(0xffffffffu, lm, 2));
                if ((lane & 3) == 0)
                    atomicMax(&rowM[wm * 32 + m * 16 + h * 8 + g], fenc(lm));
            }
        }
        __syncwarp();

        // collect candidates: score > running rowmax - 3.5 (superset of true support)
        #pragma unroll
        for (int m = 0; m < 2; m++) {
            #pragma unroll
            for (int h = 0; h < 2; h++) {
                const int r = wm * 32 + m * 16 + h * 8 + g;
                const float thr = fdec(rowM[r]) - 3.5f;
                #pragma unroll
                for (int n = 0; n < 2; n++) {
                    #pragma unroll
                    for (int e = 0; e < 2; e++) {
                        float s = acc[m][n][h * 2 + e];
                        if (s > thr) {
                            int p = atomicAdd(&cnt[r], 1);
                            if (p < CAP) {
                                candS[r * CSTR + p] = s;
                                candC[r * CSTR + p] = nt * BN + wn * 16 + n * 8 + t * 2 + e;
                            }
                        }
                    }
                }
            }
        }
    }
    __syncthreads();

    // ---- deterministic order: per-row insertion sort by column ----
    if (tid < BM) {
        const int r = tid;
        int c_ = cnt[r]; if (c_ > CAP) { c_ = CAP; cnt[r] = CAP; }
        float* cs = candS + r * CSTR;
        int*   cc = candC + r * CSTR;
        for (int i = 1; i < c_; i++) {
            float sv = cs[i]; int kv = cc[i]; int j = i - 1;
            while (j >= 0 && cc[j] > kv) { cc[j + 1] = cc[j]; cs[j + 1] = cs[j]; j--; }
            cc[j + 1] = kv; cs[j + 1] = sv;
        }
    }
    __syncthreads();

    // ---- exact fp32 rescore: warp-per-row, coalesced K row loads ----
    for (int r = wid; r < BM; r += 8) {
        const int c_ = cnt[r];
        float* cs = candS + r * CSTR;
        int*   cc = candC + r * CSTR;
        const float4 qv = *(const float4*)(Qb + (size_t)r * DIM + lane * 4);
        for (int j = 0; j < c_; j++) {
            const float4 kv = *(const float4*)(Kb + (size_t)cc[j] * DIM + lane * 4);
            float d = fmaf(qv.x, kv.x, 0.f);
            d = fmaf(qv.y, kv.y, d);
            d = fmaf(qv.z, kv.z, d);
            d = fmaf(qv.w, kv.w, d);
            #pragma unroll
            for (int s = 16; s > 0; s >>= 1)
                d += __shfl_xor_sync(0xffffffffu, d, s);
            if (lane == 0) cs[j] = d;
        }
    }
    __syncthreads();

    // ---- bisection: thread-per-row ----
    if (tid < BM) {
        const int r = tid;
        const int c_ = cnt[r];
        float* cs = candS + r * CSTR;

        float smax = -3.0e38f;
        for (int j = 0; j < c_; j++) smax = fmaxf(smax, cs[j]);

        const float zmax = 0.5f * smax;
        float tmin = zmax - 1.0f;
        float tmax = zmax - 0.022097086912079608f;   // float32(2048^-0.5)
        float tau = 0.5f * (tmin + tmax), Zv = 0.f;
        for (int it = 0; it < NITER; it++) {
            tau = 0.5f * (tmin + tmax);
            Zv = 0.f;
            for (int j = 0; j < c_; j++) {
                float dz = fmaxf(0.5f * cs[j] - tau, 0.f);
                Zv += dz * dz;
            }
            if (Zv >= 1.0f) tmin = tau; else tmax = tau;
        }
        tauA[r] = tau;
        zA[r]   = Zv;
    }
    __syncthreads();

    // ---- sparse P@V: 8 warps x 8 rows, float4 coalesced V gather ----
    for (int rr = 0; rr < 8; rr++) {
        const int r = wid * 8 + rr;
        const int c_ = cnt[r];
        const float tau = tauA[r];
        const float Zv  = zA[r];
        float ax = 0.f, ay = 0.f, az = 0.f, aw = 0.f;
        for (int j = 0; j < c_; j++) {
            float dz = fmaxf(0.5f * candS[r * CSTR + j] - tau, 0.f);
            float w = (dz * dz) / Zv;
            const float4 v = *(const float4*)(Vb + (size_t)candC[r * CSTR + j] * DIM + lane * 4);
            ax = fmaf(w, v.x, ax);
            ay = fmaf(w, v.y, ay);
            az = fmaf(w, v.z, az);
            aw = fmaf(w, v.w, aw);
        }
        *(float4*)(O + ((size_t)b * SEQ + q0 + r) * DIM + lane * 4) = make_float4(ax, ay, az, aw);
    }
}

extern "C" void kernel_launch(void* const* d_in, const int* in_sizes, int n_in,
                              void* d_out, int out_size) {
    const float* Q = (const float*)d_in[0];
    const float* K = (const float*)d_in[1];
    const float* V = (const float*)d_in[2];
    float* O = (float*)d_out;

    cvt_kernel<<<2048, 256>>>(Q, K);

    cudaFuncSetAttribute(entmax_attn_kernel,
                         cudaFuncAttributeMaxDynamicSharedMemorySize, SMEM_BYTES);
    dim3 grid(QT, BATCH);
    entmax_attn_kernel<<<grid, NTHREADS, SMEM_BYTES>>>(Q, K, V, O);
}

// round 8
// speedup vs baseline: 1.1259x; 1.1259x over previous
#include <cuda_runtime.h>
#include <cuda_bf16.h>

// SparseAttention (entmax-1.5), GB300 sm_103a. Round 7 (tcgen05 unavailable in
// this toolchain -> optimized mma.sync path):
//  - pair-wise tile processing, 4 cp.async stages: 2 barriers per 2 tiles (was 6).
//  - collect early-out: skip 8-value scan when quad-max <= threshold (~90% skip).
//  - running shared row-max threshold (superset-safe), exact fp32 rescore tail.

#define BATCH 8
#define SEQ   2048
#define DIM   128
#define BM    128
#define BN    128
#define NT    (SEQ / BN)       // 16
#define PAIRS (NT / 2)         // 8
#define QT    (SEQ / BM)       // 16
#define CAP   48
#define CSTR  49
#define QSTR  136              // bf16 row stride (128+8 pad): 16B aligned, ldsm conflict-free
#define NITER 100
#define STAGES 4
#define NTHREADS 512

#define TILE_B  (BM * QSTR * 2)                       // 34816
#define OFF_QHI  0
#define OFF_KHI  (OFF_QHI + TILE_B)                   // 34816
#define OFF_CS   (OFF_KHI + STAGES * TILE_B)          // 174080
#define OFF_CC   (OFF_CS + BM * CSTR * 4)             // 199168
#define OFF_RM   (OFF_CC + BM * CSTR * 4)             // 224256
#define OFF_CNT  (OFF_RM + BM * 4)                    // 224768
#define OFF_TAU  (OFF_CNT + BM * 4)                   // 225280
#define OFF_Z    (OFF_TAU + BM * 4)                   // 225792
#define SMEM_BYTES (OFF_Z + BM * 4)                   // 226304

__device__ __nv_bfloat16 g_Qh[BATCH * SEQ * DIM];
__device__ __nv_bfloat16 g_Kh[BATCH * SEQ * DIM];

__global__ void cvt_kernel(const float* __restrict__ Q, const float* __restrict__ K) {
    size_t i = ((size_t)blockIdx.x * blockDim.x + threadIdx.x) * 4;
    float4 q = *(const float4*)(Q + i);
    float4 k = *(const float4*)(K + i);
    __nv_bfloat162 q0, q1, k0, k1;
    q0.x = __float2bfloat16(q.x); q0.y = __float2bfloat16(q.y);
    q1.x = __float2bfloat16(q.z); q1.y = __float2bfloat16(q.w);
    k0.x = __float2bfloat16(k.x); k0.y = __float2bfloat16(k.y);
    k1.x = __float2bfloat16(k.z); k1.y = __float2bfloat16(k.w);
    *(__nv_bfloat162*)(g_Qh + i)     = q0;
    *(__nv_bfloat162*)(g_Qh + i + 2) = q1;
    *(__nv_bfloat162*)(g_Kh + i)     = k0;
    *(__nv_bfloat162*)(g_Kh + i + 2) = k1;
}

static __device__ __forceinline__ unsigned fenc(float f) {
    unsigned u = __float_as_uint(f);
    return (u & 0x80000000u) ? ~u : (u | 0x80000000u);
}
static __device__ __forceinline__ float fdec(unsigned e) {
    return (e & 0x80000000u) ? __uint_as_float(e & 0x7fffffffu)
                             : __uint_as_float(~e);
}
static __device__ __forceinline__ void cpasync16(unsigned dst, const void* src) {
    asm volatile("cp.async.cg.shared.global [%0], [%1], 16;\n" :: "r"(dst), "l"(src));
}
static __device__ __forceinline__ void cp_commit() {
    asm volatile("cp.async.commit_group;\n");
}
template <int N>
static __device__ __forceinline__ void cp_wait() {
    asm volatile("cp.async.wait_group %0;\n" :: "n"(N));
}
static __device__ __forceinline__ void ldsm4(unsigned* r, unsigned addr) {
    asm volatile("ldmatrix.sync.aligned.m8n8.x4.shared.b16 {%0,%1,%2,%3}, [%4];\n"
                 : "=r"(r[0]), "=r"(r[1]), "=r"(r[2]), "=r"(r[3])
                 : "r"(addr) : "memory");
}
static __device__ __forceinline__ void mma16816(float* c, const unsigned* a, const unsigned* b) {
    asm volatile("mma.sync.aligned.m16n8k16.row.col.f32.bf16.bf16.f32 "
                 "{%0,%1,%2,%3}, {%4,%5,%6,%7}, {%8,%9}, {%0,%1,%2,%3};\n"
                 : "+f"(c[0]), "+f"(c[1]), "+f"(c[2]), "+f"(c[3])
                 : "r"(a[0]), "r"(a[1]), "r"(a[2]), "r"(a[3]),
                   "r"(b[0]), "r"(b[1]));
}

__global__ __launch_bounds__(NTHREADS, 1)
void entmax_attn_kernel(const float* __restrict__ Q, const float* __restrict__ K,
                        const float* __restrict__ V, float* __restrict__ O)
{
    extern __shared__ unsigned char smem[];
    float*    candS = (float*)(smem + OFF_CS);
    int*      candC = (int*)(smem + OFF_CC);
    unsigned* rowM  = (unsigned*)(smem + OFF_RM);
    int*      cnt   = (int*)(smem + OFF_CNT);
    float*    tauA  = (float*)(smem + OFF_TAU);
    float*    zA    = (float*)(smem + OFF_Z);

    const int tid  = threadIdx.x;
    const int lane = tid & 31;
    const int wid  = tid >> 5;
    const int b    = blockIdx.y;
    const int q0   = blockIdx.x * BM;

    const float* Qb = Q + ((size_t)b * SEQ + q0) * DIM;
    const float* Kb = K + (size_t)b * SEQ * DIM;
    const float* Vb = V + (size_t)b * SEQ * DIM;
    const __nv_bfloat16* Qhb = g_Qh + ((size_t)b * SEQ + q0) * DIM;
    const __nv_bfloat16* Khb = g_Kh + (size_t)b * SEQ * DIM;

    const unsigned smemB = (unsigned)__cvta_generic_to_shared(smem);
    const unsigned qS = smemB + OFF_QHI;

    // 4x4 warp grid, 32x32 warp tiles
    const int wm = wid & 3;
    const int wn = wid >> 2;
    const int g  = lane >> 2;
    const int t  = lane & 3;

    const int aRow = (lane & 7) + ((lane >> 3) & 1) * 8;  // ldsm x4 (A)
    const int aK   = ((lane >> 4) & 1) * 8;
    const int bGrp  = lane >> 3;                          // ldsm x4 (B): n16 x k16
    const int bRow4 = ((bGrp >> 1) & 1) * 8 + (lane & 7);
    const int bK4   = (bGrp & 1) * 8;

    if (tid < BM) { rowM[tid] = 0u; cnt[tid] = 0; }

    const int frow0 = tid >> 4;        // 0..31
    const int fc16  = tid & 15;

    auto fill_tile = [&](const __nv_bfloat16* src, unsigned dst) {
        #pragma unroll
        for (int k = 0; k < 4; k++) {
            int r = frow0 + k * 32;
            cpasync16(dst + r * (QSTR * 2) + fc16 * 16, src + r * DIM + fc16 * 8);
        }
    };

    // prologue: Q + pair 0 (tiles 0,1) -> group; pair 1 (tiles 2,3) -> group
    fill_tile(Qhb, qS);
    fill_tile(Khb,                      smemB + OFF_KHI);
    fill_tile(Khb + (size_t)BN * DIM,   smemB + OFF_KHI + TILE_B);
    cp_commit();
    fill_tile(Khb + (size_t)2 * BN * DIM, smemB + OFF_KHI + 2 * TILE_B);
    fill_tile(Khb + (size_t)3 * BN * DIM, smemB + OFF_KHI + 3 * TILE_B);
    cp_commit();

    auto process_tile = [&](int nt) {
        const unsigned kS = smemB + OFF_KHI + (nt & 3) * TILE_B;

        float acc[2][4][4];
        #pragma unroll
        for (int m = 0; m < 2; m++)
            #pragma unroll
            for (int n = 0; n < 4; n++)
                #pragma unroll
                for (int e = 0; e < 4; e++) acc[m][n][e] = 0.f;

        #pragma unroll
        for (int ks = 0; ks < 8; ks++) {
            unsigned a[2][4], bb[2][4];
            #pragma unroll
            for (int m = 0; m < 2; m++)
                ldsm4(a[m], qS + (unsigned)(((wm * 32 + m * 16 + aRow) * QSTR + ks * 16 + aK) * 2));
            #pragma unroll
            for (int p = 0; p < 2; p++)
                ldsm4(bb[p], kS + (unsigned)(((wn * 32 + p * 16 + bRow4) * QSTR + ks * 16 + bK4) * 2));
            #pragma unroll
            for (int m = 0; m < 2; m++)
                #pragma unroll
                for (int p = 0; p < 2; p++) {
                    mma16816(acc[m][p * 2],     a[m], &bb[p][0]);
                    mma16816(acc[m][p * 2 + 1], a[m], &bb[p][2]);
                }
        }

        // per-(m,h): quad max (over all 32 cols of row r), update running rowM
        float qm[2][2];
        #pragma unroll
        for (int m = 0; m < 2; m++) {
            #pragma unroll
            for (int h = 0; h < 2; h++) {
                float lm = fmaxf(fmaxf(acc[m][0][h * 2], acc[m][0][h * 2 + 1]),
                                 fmaxf(acc[m][1][h * 2], acc[m][1][h * 2 + 1]));
                lm = fmaxf(lm, fmaxf(fmaxf(acc[m][2][h * 2], acc[m][2][h * 2 + 1]),
                                     fmaxf(acc[m][3][h * 2], acc[m][3][h * 2 + 1])));
                lm = fmaxf(lm, __shfl_xor_sync(0xffffffffu, lm, 1));
                lm = fmaxf(lm, __shfl_xor_sync(0xffffffffu, lm, 2));
                qm[m][h] = lm;
                if ((lane & 3) == 0)
                    atomicMax(&rowM[wm * 32 + m * 16 + h * 8 + g], fenc(lm));
            }
        }
        __syncwarp();

        // collect candidates; early-out whole (m,h) group when qm <= thr
        #pragma unroll
        for (int m = 0; m < 2; m++) {
            #pragma unroll
            for (int h = 0; h < 2; h++) {
                const int r = wm * 32 + m * 16 + h * 8 + g;
                const float thr = fdec(rowM[r]) - 3.5f;
                if (qm[m][h] > thr) {
                    #pragma unroll
                    for (int n = 0; n < 4; n++) {
                        #pragma unroll
                        for (int e = 0; e < 2; e++) {
                            float s = acc[m][n][h * 2 + e];
                            if (s > thr) {
                                int p = atomicAdd(&cnt[r], 1);
                                if (p < CAP) {
                                    candS[r * CSTR + p] = s;
                                    candC[r * CSTR + p] = nt * BN + wn * 32 + n * 8 + t * 2 + e;
                                }
                            }
                        }
                    }
                }
            }
        }
    };

    for (int pp = 0; pp < PAIRS; pp++) {
        if (pp < PAIRS - 1) cp_wait<1>(); else cp_wait<0>();
        __syncthreads();                 // pair pp resident (all threads' copies)

        process_tile(2 * pp);
        process_tile(2 * pp + 1);

        __syncthreads();                 // all warps done reading pair pp
        if (pp + 2 < PAIRS) {            // refill pp's stages with pair pp+2
            const int t0 = 2 * pp + 4;
            fill_tile(Khb + (size_t)t0 * BN * DIM,       smemB + OFF_KHI + (t0 & 3) * TILE_B);
            fill_tile(Khb + (size_t)(t0 + 1) * BN * DIM, smemB + OFF_KHI + ((t0 + 1) & 3) * TILE_B);
            cp_commit();
        }
    }
    __syncthreads();

    // ---- deterministic order: per-row insertion sort by column ----
    if (tid < BM) {
        const int r = tid;
        int c_ = cnt[r]; if (c_ > CAP) { c_ = CAP; cnt[r] = CAP; }
        float* cs = candS + r * CSTR;
        int*   cc = candC + r * CSTR;
        for (int i = 1; i < c_; i++) {
            float sv = cs[i]; int kv = cc[i]; int j = i - 1;
            while (j >= 0 && cc[j] > kv) { cc[j + 1] = cc[j]; cs[j + 1] = cs[j]; j--; }
            cc[j + 1] = kv; cs[j + 1] = sv;
        }
    }
    __syncthreads();

    // ---- exact fp32 rescore: warp-per-row, coalesced K row loads ----
    for (int r = wid; r < BM; r += 16) {
        const int c_ = cnt[r];
        float* cs = candS + r * CSTR;
        int*   cc = candC + r * CSTR;
        const float4 qv = *(const float4*)(Qb + (size_t)r * DIM + lane * 4);
        for (int j = 0; j < c_; j++) {
            const float4 kv = *(const float4*)(Kb + (size_t)cc[j] * DIM + lane * 4);
            float d = fmaf(qv.x, kv.x, 0.f);
            d = fmaf(qv.y, kv.y, d);
            d = fmaf(qv.z, kv.z, d);
            d = fmaf(qv.w, kv.w, d);
            #pragma unroll
            for (int s = 16; s > 0; s >>= 1)
                d += __shfl_xor_sync(0xffffffffu, d, s);
            if (lane == 0) cs[j] = d;
        }
    }
    __syncthreads();

    // ---- bisection: thread-per-row ----
    if (tid < BM) {
        const int r = tid;
        const int c_ = cnt[r];
        float* cs = candS + r * CSTR;

        float smax = -3.0e38f;
        for (int j = 0; j < c_; j++) smax = fmaxf(smax, cs[j]);

        const float zmax = 0.5f * smax;
        float tmin = zmax - 1.0f;
        float tmax = zmax - 0.022097086912079608f;   // float32(2048^-0.5)
        float tau = 0.5f * (tmin + tmax), Zv = 0.f;
        for (int it = 0; it < NITER; it++) {
            tau = 0.5f * (tmin + tmax);
            Zv = 0.f;
            for (int j = 0; j < c_; j++) {
                float dz = fmaxf(0.5f * cs[j] - tau, 0.f);
                Zv += dz * dz;
            }
            if (Zv >= 1.0f) tmin = tau; else tmax = tau;
        }
        tauA[r] = tau;
        zA[r]   = Zv;
    }
    __syncthreads();

    // ---- sparse P@V: 16 warps x 8 rows, float4 coalesced V gather ----
    for (int rr = 0; rr < 8; rr++) {
        const int r = wid * 8 + rr;
        const int c_ = cnt[r];
        const float tau = tauA[r];
        const float Zv  = zA[r];
        float ax = 0.f, ay = 0.f, az = 0.f, aw = 0.f;
        for (int j = 0; j < c_; j++) {
            float dz = fmaxf(0.5f * candS[r * CSTR + j] - tau, 0.f);
            float w = (dz * dz) / Zv;
            const float4 v = *(const float4*)(Vb + (size_t)candC[r * CSTR + j] * DIM + lane * 4);
            ax = fmaf(w, v.x, ax);
            ay = fmaf(w, v.y, ay);
            az = fmaf(w, v.z, az);
            aw = fmaf(w, v.w, aw);
        }
        *(float4*)(O + ((size_t)b * SEQ + q0 + r) * DIM + lane * 4) = make_float4(ax, ay, az, aw);
    }
}

extern "C" void kernel_launch(void* const* d_in, const int* in_sizes, int n_in,
                              void* d_out, int out_size) {
    const float* Q = (const float*)d_in[0];
    const float* K = (const float*)d_in[1];
    const float* V = (const float*)d_in[2];
    float* O = (float*)d_out;

    cvt_kernel<<<2048, 256>>>(Q, K);

    cudaFuncSetAttribute(entmax_attn_kernel,
                         cudaFuncAttributeMaxDynamicSharedMemorySize, SMEM_BYTES);
    dim3 grid(QT, BATCH);
    entmax_attn_kernel<<<grid, NTHREADS, SMEM_BYTES>>>(Q, K, V, O);
}

// round 9
// speedup vs baseline: 1.1314x; 1.0049x over previous
#include <cuda_runtime.h>
#include <cuda_fp16.h>

// SparseAttention (entmax-1.5), GB300 sm_103a. Round 8:
//  - f16-accumulate mma.sync (m16n8k16.f16): 2x legacy tensor rate (if available),
//    half the accumulator registers. Collect window 3.5 covers fp16 error ~0.2.
//  - MLP-batched tail: rescore + P@V issue 4 independent LDGs per step.
//  - pair-wise tiles, 4 cp.async stages, running rowmax threshold, early-out.

#define BATCH 8
#define SEQ   2048
#define DIM   128
#define BM    128
#define BN    128
#define NT    (SEQ / BN)       // 16
#define PAIRS (NT / 2)         // 8
#define QT    (SEQ / BM)       // 16
#define CAP   48
#define CSTR  49
#define QSTR  136              // f16 row stride (128+8 pad): 16B aligned, ldsm conflict-free
#define NITER 100
#define NTHREADS 512

#define TILE_B  (BM * QSTR * 2)                       // 34816
#define OFF_QHI  0
#define OFF_KHI  (OFF_QHI + TILE_B)                   // 34816
#define OFF_CS   (OFF_KHI + 4 * TILE_B)               // 174080
#define OFF_CC   (OFF_CS + BM * CSTR * 4)             // 199168
#define OFF_RM   (OFF_CC + BM * CSTR * 4)             // 224256
#define OFF_CNT  (OFF_RM + BM * 4)                    // 224768
#define OFF_TAU  (OFF_CNT + BM * 4)                   // 225280
#define OFF_Z    (OFF_TAU + BM * 4)                   // 225792
#define SMEM_BYTES (OFF_Z + BM * 4)                   // 226304

__device__ __half g_Qh[BATCH * SEQ * DIM];
__device__ __half g_Kh[BATCH * SEQ * DIM];

__global__ void cvt_kernel(const float* __restrict__ Q, const float* __restrict__ K) {
    size_t i = ((size_t)blockIdx.x * blockDim.x + threadIdx.x) * 4;
    float4 q = *(const float4*)(Q + i);
    float4 k = *(const float4*)(K + i);
    __half2 q0 = __floats2half2_rn(q.x, q.y);
    __half2 q1 = __floats2half2_rn(q.z, q.w);
    __half2 k0 = __floats2half2_rn(k.x, k.y);
    __half2 k1 = __floats2half2_rn(k.z, k.w);
    *(__half2*)(g_Qh + i)     = q0;
    *(__half2*)(g_Qh + i + 2) = q1;
    *(__half2*)(g_Kh + i)     = k0;
    *(__half2*)(g_Kh + i + 2) = k1;
}

static __device__ __forceinline__ unsigned fenc(float f) {
    unsigned u = __float_as_uint(f);
    return (u & 0x80000000u) ? ~u : (u | 0x80000000u);
}
static __device__ __forceinline__ float fdec(unsigned e) {
    return (e & 0x80000000u) ? __uint_as_float(e & 0x7fffffffu)
                             : __uint_as_float(~e);
}
static __device__ __forceinline__ void cpasync16(unsigned dst, const void* src) {
    asm volatile("cp.async.cg.shared.global [%0], [%1], 16;\n" :: "r"(dst), "l"(src));
}
static __device__ __forceinline__ void cp_commit() {
    asm volatile("cp.async.commit_group;\n");
}
template <int N>
static __device__ __forceinline__ void cp_wait() {
    asm volatile("cp.async.wait_group %0;\n" :: "n"(N));
}
static __device__ __forceinline__ void ldsm4(unsigned* r, unsigned addr) {
    asm volatile("ldmatrix.sync.aligned.m8n8.x4.shared.b16 {%0,%1,%2,%3}, [%4];\n"
                 : "=r"(r[0]), "=r"(r[1]), "=r"(r[2]), "=r"(r[3])
                 : "r"(addr) : "memory");
}
// f16 in, f16 accumulate: D (2 regs = 4 halves)
static __device__ __forceinline__ void mma16816h(unsigned* c, const unsigned* a, const unsigned* b) {
    asm volatile("mma.sync.aligned.m16n8k16.row.col.f16.f16.f16.f16 "
                 "{%0,%1}, {%2,%3,%4,%5}, {%6,%7}, {%0,%1};\n"
                 : "+r"(c[0]), "+r"(c[1])
                 : "r"(a[0]), "r"(a[1]), "r"(a[2]), "r"(a[3]),
                   "r"(b[0]), "r"(b[1]));
}

__global__ __launch_bounds__(NTHREADS, 1)
void entmax_attn_kernel(const float* __restrict__ Q, const float* __restrict__ K,
                        const float* __restrict__ V, float* __restrict__ O)
{
    extern __shared__ unsigned char smem[];
    float*    candS = (float*)(smem + OFF_CS);
    int*      candC = (int*)(smem + OFF_CC);
    unsigned* rowM  = (unsigned*)(smem + OFF_RM);
    int*      cnt   = (int*)(smem + OFF_CNT);
    float*    tauA  = (float*)(smem + OFF_TAU);
    float*    zA    = (float*)(smem + OFF_Z);

    const int tid  = threadIdx.x;
    const int lane = tid & 31;
    const int wid  = tid >> 5;
    const int b    = blockIdx.y;
    const int q0   = blockIdx.x * BM;

    const float* Qb = Q + ((size_t)b * SEQ + q0) * DIM;
    const float* Kb = K + (size_t)b * SEQ * DIM;
    const float* Vb = V + (size_t)b * SEQ * DIM;
    const __half* Qhb = g_Qh + ((size_t)b * SEQ + q0) * DIM;
    const __half* Khb = g_Kh + (size_t)b * SEQ * DIM;

    const unsigned smemB = (unsigned)__cvta_generic_to_shared(smem);
    const unsigned qS = smemB + OFF_QHI;

    // 4x4 warp grid, 32x32 warp tiles
    const int wm = wid & 3;
    const int wn = wid >> 2;
    const int g  = lane >> 2;
    const int t  = lane & 3;

    const int aRow = (lane & 7) + ((lane >> 3) & 1) * 8;  // ldsm x4 (A)
    const int aK   = ((lane >> 4) & 1) * 8;
    const int bGrp  = lane >> 3;                          // ldsm x4 (B): n16 x k16
    const int bRow4 = ((bGrp >> 1) & 1) * 8 + (lane & 7);
    const int bK4   = (bGrp & 1) * 8;

    if (tid < BM) { rowM[tid] = 0u; cnt[tid] = 0; }

    const int frow0 = tid >> 4;        // 0..31
    const int fc16  = tid & 15;

    auto fill_tile = [&](const __half* src, unsigned dst) {
        #pragma unroll
        for (int k = 0; k < 4; k++) {
            int r = frow0 + k * 32;
            cpasync16(dst + r * (QSTR * 2) + fc16 * 16, src + r * DIM + fc16 * 8);
        }
    };

    fill_tile(Qhb, qS);
    fill_tile(Khb,                        smemB + OFF_KHI);
    fill_tile(Khb + (size_t)BN * DIM,     smemB + OFF_KHI + TILE_B);
    cp_commit();
    fill_tile(Khb + (size_t)2 * BN * DIM, smemB + OFF_KHI + 2 * TILE_B);
    fill_tile(Khb + (size_t)3 * BN * DIM, smemB + OFF_KHI + 3 * TILE_B);
    cp_commit();

    auto process_tile = [&](int nt) {
        const unsigned kS = smemB + OFF_KHI + (nt & 3) * TILE_B;

        // f16 accumulators: [m][n][h] -> half2 (cols t*2, t*2+1; h: rows g / g+8)
        unsigned acc[2][4][2];
        #pragma unroll
        for (int m = 0; m < 2; m++)
            #pragma unroll
            for (int n = 0; n < 4; n++) { acc[m][n][0] = 0u; acc[m][n][1] = 0u; }

        #pragma unroll
        for (int ks = 0; ks < 8; ks++) {
            unsigned a[2][4], bb[2][4];
            #pragma unroll
            for (int m = 0; m < 2; m++)
                ldsm4(a[m], qS + (unsigned)(((wm * 32 + m * 16 + aRow) * QSTR + ks * 16 + aK) * 2));
            #pragma unroll
            for (int p = 0; p < 2; p++)
                ldsm4(bb[p], kS + (unsigned)(((wn * 32 + p * 16 + bRow4) * QSTR + ks * 16 + bK4) * 2));
            #pragma unroll
            for (int m = 0; m < 2; m++)
                #pragma unroll
                for (int p = 0; p < 2; p++) {
                    mma16816h(acc[m][p * 2],     a[m], &bb[p][0]);
                    mma16816h(acc[m][p * 2 + 1], a[m], &bb[p][2]);
                }
        }

        // per-(m,h) quad max over 32 cols, update running rowM
        float qm[2][2];
        #pragma unroll
        for (int m = 0; m < 2; m++) {
            #pragma unroll
            for (int h = 0; h < 2; h++) {
                __half2 x = __hmax2(*(__half2*)&acc[m][0][h], *(__half2*)&acc[m][1][h]);
                __half2 y = __hmax2(*(__half2*)&acc[m][2][h], *(__half2*)&acc[m][3][h]);
                x = __hmax2(x, y);
                float2 f = __half22float2(x);
                float lm = fmaxf(f.x, f.y);
                lm = fmaxf(lm, __shfl_xor_sync(0xffffffffu, lm, 1));
                lm = fmaxf(lm, __shfl_xor_sync(0xffffffffu, lm, 2));
                qm[m][h] = lm;
                if ((lane & 3) == 0)
                    atomicMax(&rowM[wm * 32 + m * 16 + h * 8 + g], fenc(lm));
            }
        }
        __syncwarp();

        // collect; early-out whole (m,h) group when quad-max <= threshold
        #pragma unroll
        for (int m = 0; m < 2; m++) {
            #pragma unroll
            for (int h = 0; h < 2; h++) {
                const int r = wm * 32 + m * 16 + h * 8 + g;
                const float thr = fdec(rowM[r]) - 3.5f;
                if (qm[m][h] > thr) {
                    #pragma unroll
                    for (int n = 0; n < 4; n++) {
                        float2 f = __half22float2(*(__half2*)&acc[m][n][h]);
                        #pragma unroll
                        for (int e = 0; e < 2; e++) {
                            float s = (e == 0) ? f.x : f.y;
                            if (s > thr) {
                                int p = atomicAdd(&cnt[r], 1);
                                if (p < CAP) {
                                    candS[r * CSTR + p] = s;
                                    candC[r * CSTR + p] = nt * BN + wn * 32 + n * 8 + t * 2 + e;
                                }
                            }
                        }
                    }
                }
            }
        }
    };

    for (int pp = 0; pp < PAIRS; pp++) {
        if (pp < PAIRS - 1) cp_wait<1>(); else cp_wait<0>();
        __syncthreads();                 // pair pp resident

        process_tile(2 * pp);
        process_tile(2 * pp + 1);

        __syncthreads();                 // all warps done reading pair pp
        if (pp + 2 < PAIRS) {
            const int t0 = 2 * pp + 4;
            fill_tile(Khb + (size_t)t0 * BN * DIM,       smemB + OFF_KHI + (t0 & 3) * TILE_B);
            fill_tile(Khb + (size_t)(t0 + 1) * BN * DIM, smemB + OFF_KHI + ((t0 + 1) & 3) * TILE_B);
            cp_commit();
        }
    }
    __syncthreads();

    // ---- deterministic order: per-row insertion sort by column ----
    if (tid < BM) {
        const int r = tid;
        int c_ = cnt[r]; if (c_ > CAP) { c_ = CAP; cnt[r] = CAP; }
        float* cs = candS + r * CSTR;
        int*   cc = candC + r * CSTR;
        for (int i = 1; i < c_; i++) {
            float sv = cs[i]; int kv = cc[i]; int j = i - 1;
            while (j >= 0 && cc[j] > kv) { cc[j + 1] = cc[j]; cs[j + 1] = cs[j]; j--; }
            cc[j + 1] = kv; cs[j + 1] = sv;
        }
    }
    __syncthreads();

    // ---- exact fp32 rescore: warp-per-row, 4-way batched LDG + interleaved reduce ----
    for (int r = wid; r < BM; r += 16) {
        const int c_ = cnt[r];
        float* cs = candS + r * CSTR;
        int*   cc = candC + r * CSTR;
        const float4 qv = *(const float4*)(Qb + (size_t)r * DIM + lane * 4);
        for (int j0 = 0; j0 < c_; j0 += 4) {
            float4 kv[4];
            #pragma unroll
            for (int u = 0; u < 4; u++) {
                int j = j0 + u; if (j >= c_) j = c_ - 1;      // clamped (safe, discarded)
                kv[u] = *(const float4*)(Kb + (size_t)cc[j] * DIM + lane * 4);
            }
            float d[4];
            #pragma unroll
            for (int u = 0; u < 4; u++) {
                float s = fmaf(qv.x, kv[u].x, 0.f);
                s = fmaf(qv.y, kv[u].y, s);
                s = fmaf(qv.z, kv[u].z, s);
                d[u] = fmaf(qv.w, kv[u].w, s);
            }
            #pragma unroll
            for (int s = 16; s > 0; s >>= 1) {
                d[0] += __shfl_xor_sync(0xffffffffu, d[0], s);
                d[1] += __shfl_xor_sync(0xffffffffu, d[1], s);
                d[2] += __shfl_xor_sync(0xffffffffu, d[2], s);
                d[3] += __shfl_xor_sync(0xffffffffu, d[3], s);
            }
            if (lane == 0) {
                #pragma unroll
                for (int u = 0; u < 4; u++)
                    if (j0 + u < c_) cs[j0 + u] = d[u];
            }
        }
    }
    __syncthreads();

    // ---- bisection: thread-per-row ----
    if (tid < BM) {
        const int r = tid;
        const int c_ = cnt[r];
        float* cs = candS + r * CSTR;

        float smax = -3.0e38f;
        for (int j = 0; j < c_; j++) smax = fmaxf(smax, cs[j]);

        const float zmax = 0.5f * smax;
        float tmin = zmax - 1.0f;
        float tmax = zmax - 0.022097086912079608f;   // float32(2048^-0.5)
        float tau = 0.5f * (tmin + tmax), Zv = 0.f;
        for (int it = 0; it < NITER; it++) {
            tau = 0.5f * (tmin + tmax);
            Zv = 0.f;
            for (int j = 0; j < c_; j++) {
                float dz = fmaxf(0.5f * cs[j] - tau, 0.f);
                Zv += dz * dz;
            }
            if (Zv >= 1.0f) tmin = tau; else tmax = tau;
        }
        tauA[r] = tau;
        zA[r]   = Zv;
    }
    __syncthreads();

    // ---- sparse P@V: 16 warps x 8 rows, 4-way batched V gather ----
    for (int rr = 0; rr < 8; rr++) {
        const int r = wid * 8 + rr;
        const int c_ = cnt[r];
        const float tau = tauA[r];
        const float Zv  = zA[r];
        float ax = 0.f, ay = 0.f, az = 0.f, aw = 0.f;
        for (int j0 = 0; j0 < c_; j0 += 4) {
            float4 v[4]; float w[4];
            #pragma unroll
            for (int u = 0; u < 4; u++) {
                int j = j0 + u;
                bool ok = (j < c_);
                int jc = ok ? j : (c_ - 1);
                float dz = fmaxf(0.5f * candS[r * CSTR + jc] - tau, 0.f);
                w[u] = ok ? (dz * dz) / Zv : 0.f;
                v[u] = *(const float4*)(Vb + (size_t)candC[r * CSTR + jc] * DIM + lane * 4);
            }
            #pragma unroll
            for (int u = 0; u < 4; u++) {
                ax = fmaf(w[u], v[u].x, ax);
                ay = fmaf(w[u], v[u].y, ay);
                az = fmaf(w[u], v[u].z, az);
                aw = fmaf(w[u], v[u].w, aw);
            }
        }
        *(float4*)(O + ((size_t)b * SEQ + q0 + r) * DIM + lane * 4) = make_float4(ax, ay, az, aw);
    }
}

extern "C" void kernel_launch(void* const* d_in, const int* in_sizes, int n_in,
                              void* d_out, int out_size) {
    const float* Q = (const float*)d_in[0];
    const float* K = (const float*)d_in[1];
    const float* V = (const float*)d_in[2];
    float* O = (float*)d_out;

    cvt_kernel<<<2048, 256>>>(Q, K);

    cudaFuncSetAttribute(entmax_attn_kernel,
                         cudaFuncAttributeMaxDynamicSharedMemorySize, SMEM_BYTES);
    dim3 grid(QT, BATCH);
    entmax_attn_kernel<<<grid, NTHREADS, SMEM_BYTES>>>(Q, K, V, O);
}

// round 10
// speedup vs baseline: 1.2533x; 1.1077x over previous
#include <cuda_runtime.h>
#include <cuda_fp16.h>

// SparseAttention (entmax-1.5), GB300 sm_103a. Round 9:
//  - 1024 threads / 32 warps (8 per SMSP) — first real test of issue-latency
//    hiding on the post-tail-fix structure. Warp grid 4x8, warp tile 32x16.
//  - f16-accum mma.sync, pair-wise tiles, 4 cp.async stages, running rowmax
//    threshold with early-out collect, exact fp32 rescore tail (unchanged math).

#define BATCH 8
#define SEQ   2048
#define DIM   128
#define BM    128
#define BN    128
#define NT    (SEQ / BN)       // 16
#define PAIRS (NT / 2)         // 8
#define QT    (SEQ / BM)       // 16
#define CAP   48
#define CSTR  49
#define QSTR  136              // f16 row stride (128+8 pad): 16B aligned, ldsm conflict-free
#define NITER 100
#define NTHREADS 1024

#define TILE_B  (BM * QSTR * 2)                       // 34816
#define OFF_QHI  0
#define OFF_KHI  (OFF_QHI + TILE_B)                   // 34816
#define OFF_CS   (OFF_KHI + 4 * TILE_B)               // 174080
#define OFF_CC   (OFF_CS + BM * CSTR * 4)             // 199168
#define OFF_RM   (OFF_CC + BM * CSTR * 4)             // 224256
#define OFF_CNT  (OFF_RM + BM * 4)                    // 224768
#define OFF_TAU  (OFF_CNT + BM * 4)                   // 225280
#define OFF_Z    (OFF_TAU + BM * 4)                   // 225792
#define SMEM_BYTES (OFF_Z + BM * 4)                   // 226304

__device__ __half g_Qh[BATCH * SEQ * DIM];
__device__ __half g_Kh[BATCH * SEQ * DIM];

__global__ void cvt_kernel(const float* __restrict__ Q, const float* __restrict__ K) {
    size_t i = ((size_t)blockIdx.x * blockDim.x + threadIdx.x) * 4;
    float4 q = *(const float4*)(Q + i);
    float4 k = *(const float4*)(K + i);
    *(__half2*)(g_Qh + i)     = __floats2half2_rn(q.x, q.y);
    *(__half2*)(g_Qh + i + 2) = __floats2half2_rn(q.z, q.w);
    *(__half2*)(g_Kh + i)     = __floats2half2_rn(k.x, k.y);
    *(__half2*)(g_Kh + i + 2) = __floats2half2_rn(k.z, k.w);
}

static __device__ __forceinline__ unsigned fenc(float f) {
    unsigned u = __float_as_uint(f);
    return (u & 0x80000000u) ? ~u : (u | 0x80000000u);
}
static __device__ __forceinline__ float fdec(unsigned e) {
    return (e & 0x80000000u) ? __uint_as_float(e & 0x7fffffffu)
                             : __uint_as_float(~e);
}
static __device__ __forceinline__ void cpasync16(unsigned dst, const void* src) {
    asm volatile("cp.async.cg.shared.global [%0], [%1], 16;\n" :: "r"(dst), "l"(src));
}
static __device__ __forceinline__ void cp_commit() {
    asm volatile("cp.async.commit_group;\n");
}
template <int N>
static __device__ __forceinline__ void cp_wait() {
    asm volatile("cp.async.wait_group %0;\n" :: "n"(N));
}
static __device__ __forceinline__ void ldsm4(unsigned* r, unsigned addr) {
    asm volatile("ldmatrix.sync.aligned.m8n8.x4.shared.b16 {%0,%1,%2,%3}, [%4];\n"
                 : "=r"(r[0]), "=r"(r[1]), "=r"(r[2]), "=r"(r[3])
                 : "r"(addr) : "memory");
}
static __device__ __forceinline__ void mma16816h(unsigned* c, const unsigned* a, const unsigned* b) {
    asm volatile("mma.sync.aligned.m16n8k16.row.col.f16.f16.f16.f16 "
                 "{%0,%1}, {%2,%3,%4,%5}, {%6,%7}, {%0,%1};\n"
                 : "+r"(c[0]), "+r"(c[1])
                 : "r"(a[0]), "r"(a[1]), "r"(a[2]), "r"(a[3]),
                   "r"(b[0]), "r"(b[1]));
}

__global__ __launch_bounds__(NTHREADS, 1)
void entmax_attn_kernel(const float* __restrict__ Q, const float* __restrict__ K,
                        const float* __restrict__ V, float* __restrict__ O)
{
    extern __shared__ unsigned char smem[];
    float*    candS = (float*)(smem + OFF_CS);
    int*      candC = (int*)(smem + OFF_CC);
    unsigned* rowM  = (unsigned*)(smem + OFF_RM);
    int*      cnt   = (int*)(smem + OFF_CNT);
    float*    tauA  = (float*)(smem + OFF_TAU);
    float*    zA    = (float*)(smem + OFF_Z);

    const int tid  = threadIdx.x;
    const int lane = tid & 31;
    const int wid  = tid >> 5;
    const int b    = blockIdx.y;
    const int q0   = blockIdx.x * BM;

    const float* Qb = Q + ((size_t)b * SEQ + q0) * DIM;
    const float* Kb = K + (size_t)b * SEQ * DIM;
    const float* Vb = V + (size_t)b * SEQ * DIM;
    const __half* Qhb = g_Qh + ((size_t)b * SEQ + q0) * DIM;
    const __half* Khb = g_Kh + (size_t)b * SEQ * DIM;

    const unsigned smemB = (unsigned)__cvta_generic_to_shared(smem);
    const unsigned qS = smemB + OFF_QHI;

    // 4x8 warp grid: warp tile 32(M) x 16(N)
    const int wm = wid & 3;          // 4 warps in M (32 rows each)
    const int wn = wid >> 2;         // 8 warps in N (16 cols each)
    const int g  = lane >> 2;
    const int t  = lane & 3;

    const int aRow = (lane & 7) + ((lane >> 3) & 1) * 8;  // ldsm x4 (A)
    const int aK   = ((lane >> 4) & 1) * 8;
    const int bGrp  = lane >> 3;                          // ldsm x4 (B): n16 x k16
    const int bRow4 = ((bGrp >> 1) & 1) * 8 + (lane & 7);
    const int bK4   = (bGrp & 1) * 8;

    if (tid < BM) { rowM[tid] = 0u; cnt[tid] = 0; }

    const int frow0 = tid >> 4;        // 0..63
    const int fc16  = tid & 15;

    auto fill_tile = [&](const __half* src, unsigned dst) {
        #pragma unroll
        for (int k = 0; k < 2; k++) {
            int r = frow0 + k * 64;
            cpasync16(dst + r * (QSTR * 2) + fc16 * 16, src + r * DIM + fc16 * 8);
        }
    };

    fill_tile(Qhb, qS);
    fill_tile(Khb,                        smemB + OFF_KHI);
    fill_tile(Khb + (size_t)BN * DIM,     smemB + OFF_KHI + TILE_B);
    cp_commit();
    fill_tile(Khb + (size_t)2 * BN * DIM, smemB + OFF_KHI + 2 * TILE_B);
    fill_tile(Khb + (size_t)3 * BN * DIM, smemB + OFF_KHI + 3 * TILE_B);
    cp_commit();

    auto process_tile = [&](int nt) {
        const unsigned kS = smemB + OFF_KHI + (nt & 3) * TILE_B;

        // f16 accumulators: [m][n][h] -> half2 (cols t*2,t*2+1; h: rows g / g+8)
        unsigned acc[2][2][2];
        #pragma unroll
        for (int m = 0; m < 2; m++)
            #pragma unroll
            for (int n = 0; n < 2; n++) { acc[m][n][0] = 0u; acc[m][n][1] = 0u; }

        #pragma unroll
        for (int ks = 0; ks < 8; ks++) {
            unsigned a[2][4], bb[4];
            #pragma unroll
            for (int m = 0; m < 2; m++)
                ldsm4(a[m], qS + (unsigned)(((wm * 32 + m * 16 + aRow) * QSTR + ks * 16 + aK) * 2));
            ldsm4(bb, kS + (unsigned)(((wn * 16 + bRow4) * QSTR + ks * 16 + bK4) * 2));
            #pragma unroll
            for (int m = 0; m < 2; m++) {
                mma16816h(acc[m][0], a[m], &bb[0]);
                mma16816h(acc[m][1], a[m], &bb[2]);
            }
        }

        // per-(m,h) quad max over this warp's 16 cols, update running rowM
        float qm[2][2];
        #pragma unroll
        for (int m = 0; m < 2; m++) {
            #pragma unroll
            for (int h = 0; h < 2; h++) {
                __half2 x = __hmax2(*(__half2*)&acc[m][0][h], *(__half2*)&acc[m][1][h]);
                float2 f = __half22float2(x);
                float lm = fmaxf(f.x, f.y);
                lm = fmaxf(lm, __shfl_xor_sync(0xffffffffu, lm, 1));
                lm = fmaxf(lm, __shfl_xor_sync(0xffffffffu, lm, 2));
                qm[m][h] = lm;
                if ((lane & 3) == 0)
                    atomicMax(&rowM[wm * 32 + m * 16 + h * 8 + g], fenc(lm));
            }
        }
        __syncwarp();

        // collect; early-out whole (m,h) group when quad-max <= threshold
        #pragma unroll
        for (int m = 0; m < 2; m++) {
            #pragma unroll
            for (int h = 0; h < 2; h++) {
                const int r = wm * 32 + m * 16 + h * 8 + g;
                const float thr = fdec(rowM[r]) - 3.5f;
                if (qm[m][h] > thr) {
                    #pragma unroll
                    for (int n = 0; n < 2; n++) {
                        float2 f = __half22float2(*(__half2*)&acc[m][n][h]);
                        #pragma unroll
                        for (int e = 0; e < 2; e++) {
                            float s = (e == 0) ? f.x : f.y;
                            if (s > thr) {
                                int p = atomicAdd(&cnt[r], 1);
                                if (p < CAP) {
                                    candS[r * CSTR + p] = s;
                                    candC[r * CSTR + p] = nt * BN + wn * 16 + n * 8 + t * 2 + e;
                                }
                            }
                        }
                    }
                }
            }
        }
    };

    for (int pp = 0; pp < PAIRS; pp++) {
        if (pp < PAIRS - 1) cp_wait<1>(); else cp_wait<0>();
        __syncthreads();                 // pair pp resident

        process_tile(2 * pp);
        process_tile(2 * pp + 1);

        __syncthreads();                 // all warps done reading pair pp
        if (pp + 2 < PAIRS) {
            const int t0 = 2 * pp + 4;
            fill_tile(Khb + (size_t)t0 * BN * DIM,       smemB + OFF_KHI + (t0 & 3) * TILE_B);
            fill_tile(Khb + (size_t)(t0 + 1) * BN * DIM, smemB + OFF_KHI + ((t0 + 1) & 3) * TILE_B);
            cp_commit();
        }
    }
    __syncthreads();

    // ---- deterministic order: per-row insertion sort by column ----
    if (tid < BM) {
        const int r = tid;
        int c_ = cnt[r]; if (c_ > CAP) { c_ = CAP; cnt[r] = CAP; }
        float* cs = candS + r * CSTR;
        int*   cc = candC + r * CSTR;
        for (int i = 1; i < c_; i++) {
            float sv = cs[i]; int kv = cc[i]; int j = i - 1;
            while (j >= 0 && cc[j] > kv) { cc[j + 1] = cc[j]; cs[j + 1] = cs[j]; j--; }
            cc[j + 1] = kv; cs[j + 1] = sv;
        }
    }
    __syncthreads();

    // ---- exact fp32 rescore: warp-per-row (4 rows/warp), 4-way batched LDG ----
    for (int r = wid; r < BM; r += 32) {
        const int c_ = cnt[r];
        float* cs = candS + r * CSTR;
        int*   cc = candC + r * CSTR;
        const float4 qv = *(const float4*)(Qb + (size_t)r * DIM + lane * 4);
        for (int j0 = 0; j0 < c_; j0 += 4) {
            float4 kv[4];
            #pragma unroll
            for (int u = 0; u < 4; u++) {
                int j = j0 + u; if (j >= c_) j = c_ - 1;
                kv[u] = *(const float4*)(Kb + (size_t)cc[j] * DIM + lane * 4);
            }
            float d[4];
            #pragma unroll
            for (int u = 0; u < 4; u++) {
                float s = fmaf(qv.x, kv[u].x, 0.f);
                s = fmaf(qv.y, kv[u].y, s);
                s = fmaf(qv.z, kv[u].z, s);
                d[u] = fmaf(qv.w, kv[u].w, s);
            }
            #pragma unroll
            for (int s = 16; s > 0; s >>= 1) {
                d[0] += __shfl_xor_sync(0xffffffffu, d[0], s);
                d[1] += __shfl_xor_sync(0xffffffffu, d[1], s);
                d[2] += __shfl_xor_sync(0xffffffffu, d[2], s);
                d[3] += __shfl_xor_sync(0xffffffffu, d[3], s);
            }
            if (lane == 0) {
                #pragma unroll
                for (int u = 0; u < 4; u++)
                    if (j0 + u < c_) cs[j0 + u] = d[u];
            }
        }
    }
    __syncthreads();

    // ---- bisection: thread-per-row ----
    if (tid < BM) {
        const int r = tid;
        const int c_ = cnt[r];
        float* cs = candS + r * CSTR;

        float smax = -3.0e38f;
        for (int j = 0; j < c_; j++) smax = fmaxf(smax, cs[j]);

        const float zmax = 0.5f * smax;
        float tmin = zmax - 1.0f;
        float tmax = zmax - 0.022097086912079608f;   // float32(2048^-0.5)
        float tau = 0.5f * (tmin + tmax), Zv = 0.f;
        for (int it = 0; it < NITER; it++) {
            tau = 0.5f * (tmin + tmax);
            Zv = 0.f;
            for (int j = 0; j < c_; j++) {
                float dz = fmaxf(0.5f * cs[j] - tau, 0.f);
                Zv += dz * dz;
            }
            if (Zv >= 1.0f) tmin = tau; else tmax = tau;
        }
        tauA[r] = tau;
        zA[r]   = Zv;
    }
    __syncthreads();

    // ---- sparse P@V: 32 warps x 4 rows, 4-way batched V gather ----
    for (int rr = 0; rr < 4; rr++) {
        const int r = wid * 4 + rr;
        const int c_ = cnt[r];
        const float tau = tauA[r];
        const float Zv  = zA[r];
        float ax = 0.f, ay = 0.f, az = 0.f, aw = 0.f;
        for (int j0 = 0; j0 < c_; j0 += 4) {
            float4 v[4]; float w[4];
            #pragma unroll
            for (int u = 0; u < 4; u++) {
                int j = j0 + u;
                bool ok = (j < c_);
                int jc = ok ? j : (c_ - 1);
                float dz = fmaxf(0.5f * candS[r * CSTR + jc] - tau, 0.f);
                w[u] = ok ? (dz * dz) / Zv : 0.f;
                v[u] = *(const float4*)(Vb + (size_t)candC[r * CSTR + jc] * DIM + lane * 4);
            }
            #pragma unroll
            for (int u = 0; u < 4; u++) {
                ax = fmaf(w[u], v[u].x, ax);
                ay = fmaf(w[u], v[u].y, ay);
                az = fmaf(w[u], v[u].z, az);
                aw = fmaf(w[u], v[u].w, aw);
            }
        }
        *(float4*)(O + ((size_t)b * SEQ + q0 + r) * DIM + lane * 4) = make_float4(ax, ay, az, aw);
    }
}

extern "C" void kernel_launch(void* const* d_in, const int* in_sizes, int n_in,
                              void* d_out, int out_size) {
    const float* Q = (const float*)d_in[0];
    const float* K = (const float*)d_in[1];
    const float* V = (const float*)d_in[2];
    float* O = (float*)d_out;

    cvt_kernel<<<2048, 256>>>(Q, K);

    cudaFuncSetAttribute(entmax_attn_kernel,
                         cudaFuncAttributeMaxDynamicSharedMemorySize, SMEM_BYTES);
    dim3 grid(QT, BATCH);
    entmax_attn_kernel<<<grid, NTHREADS, SMEM_BYTES>>>(Q, K, V, O);
}

// round 11
// speedup vs baseline: 1.2952x; 1.0335x over previous
#include <cuda_runtime.h>
#include <cuda_fp16.h>

// SparseAttention (entmax-1.5), GB300 sm_103a. Round 10:
//  - ks-outer pair processing: A fragments loaded once per ks for BOTH tiles
//    of a pair (halves A-LDSM traffic).
//  - register-resident bisection (z[12] padded with -3e38): removes ~600
//    serialized LDS per row from the 100-iter loop.
//  - guarded atomicMax on running row max.
//  - 1024 threads / 32 warps, f16-accum mma.sync, 4 cp.async stages.

#define BATCH 8
#define SEQ   2048
#define DIM   128
#define BM    128
#define BN    128
#define NT    (SEQ / BN)       // 16
#define PAIRS (NT / 2)         // 8
#define QT    (SEQ / BM)       // 16
#define CAP   48
#define CSTR  49
#define QSTR  136              // f16 row stride (128+8 pad): 16B aligned, ldsm conflict-free
#define NITER 100
#define NTHREADS 1024
#define ZREG  12

#define TILE_B  (BM * QSTR * 2)                       // 34816
#define OFF_QHI  0
#define OFF_KHI  (OFF_QHI + TILE_B)                   // 34816
#define OFF_CS   (OFF_KHI + 4 * TILE_B)               // 174080
#define OFF_CC   (OFF_CS + BM * CSTR * 4)             // 199168
#define OFF_RM   (OFF_CC + BM * CSTR * 4)             // 224256
#define OFF_CNT  (OFF_RM + BM * 4)                    // 224768
#define OFF_TAU  (OFF_CNT + BM * 4)                   // 225280
#define OFF_Z    (OFF_TAU + BM * 4)                   // 225792
#define SMEM_BYTES (OFF_Z + BM * 4)                   // 226304

__device__ __half g_Qh[BATCH * SEQ * DIM];
__device__ __half g_Kh[BATCH * SEQ * DIM];

__global__ void cvt_kernel(const float* __restrict__ Q, const float* __restrict__ K) {
    size_t i = ((size_t)blockIdx.x * blockDim.x + threadIdx.x) * 4;
    float4 q = *(const float4*)(Q + i);
    float4 k = *(const float4*)(K + i);
    *(__half2*)(g_Qh + i)     = __floats2half2_rn(q.x, q.y);
    *(__half2*)(g_Qh + i + 2) = __floats2half2_rn(q.z, q.w);
    *(__half2*)(g_Kh + i)     = __floats2half2_rn(k.x, k.y);
    *(__half2*)(g_Kh + i + 2) = __floats2half2_rn(k.z, k.w);
}

static __device__ __forceinline__ unsigned fenc(float f) {
    unsigned u = __float_as_uint(f);
    return (u & 0x80000000u) ? ~u : (u | 0x80000000u);
}
static __device__ __forceinline__ float fdec(unsigned e) {
    return (e & 0x80000000u) ? __uint_as_float(e & 0x7fffffffu)
                             : __uint_as_float(~e);
}
static __device__ __forceinline__ void cpasync16(unsigned dst, const void* src) {
    asm volatile("cp.async.cg.shared.global [%0], [%1], 16;\n" :: "r"(dst), "l"(src));
}
static __device__ __forceinline__ void cp_commit() {
    asm volatile("cp.async.commit_group;\n");
}
template <int N>
static __device__ __forceinline__ void cp_wait() {
    asm volatile("cp.async.wait_group %0;\n" :: "n"(N));
}
static __device__ __forceinline__ void ldsm4(unsigned* r, unsigned addr) {
    asm volatile("ldmatrix.sync.aligned.m8n8.x4.shared.b16 {%0,%1,%2,%3}, [%4];\n"
                 : "=r"(r[0]), "=r"(r[1]), "=r"(r[2]), "=r"(r[3])
                 : "r"(addr) : "memory");
}
static __device__ __forceinline__ void mma16816h(unsigned* c, const unsigned* a, const unsigned* b) {
    asm volatile("mma.sync.aligned.m16n8k16.row.col.f16.f16.f16.f16 "
                 "{%0,%1}, {%2,%3,%4,%5}, {%6,%7}, {%0,%1};\n"
                 : "+r"(c[0]), "+r"(c[1])
                 : "r"(a[0]), "r"(a[1]), "r"(a[2]), "r"(a[3]),
                   "r"(b[0]), "r"(b[1]));
}

__global__ __launch_bounds__(NTHREADS, 1)
void entmax_attn_kernel(const float* __restrict__ Q, const float* __restrict__ K,
                        const float* __restrict__ V, float* __restrict__ O)
{
    extern __shared__ unsigned char smem[];
    float*    candS = (float*)(smem + OFF_CS);
    int*      candC = (int*)(smem + OFF_CC);
    unsigned* rowM  = (unsigned*)(smem + OFF_RM);
    int*      cnt   = (int*)(smem + OFF_CNT);
    float*    tauA  = (float*)(smem + OFF_TAU);
    float*    zA    = (float*)(smem + OFF_Z);

    const int tid  = threadIdx.x;
    const int lane = tid & 31;
    const int wid  = tid >> 5;
    const int b    = blockIdx.y;
    const int q0   = blockIdx.x * BM;

    const float* Qb = Q + ((size_t)b * SEQ + q0) * DIM;
    const float* Kb = K + (size_t)b * SEQ * DIM;
    const float* Vb = V + (size_t)b * SEQ * DIM;
    const __half* Qhb = g_Qh + ((size_t)b * SEQ + q0) * DIM;
    const __half* Khb = g_Kh + (size_t)b * SEQ * DIM;

    const unsigned smemB = (unsigned)__cvta_generic_to_shared(smem);
    const unsigned qS = smemB + OFF_QHI;

    // 4x8 warp grid: warp tile 32(M) x 16(N)
    const int wm = wid & 3;
    const int wn = wid >> 2;
    const int g  = lane >> 2;
    const int t  = lane & 3;

    const int aRow = (lane & 7) + ((lane >> 3) & 1) * 8;  // ldsm x4 (A)
    const int aK   = ((lane >> 4) & 1) * 8;
    const int bGrp  = lane >> 3;                          // ldsm x4 (B): n16 x k16
    const int bRow4 = ((bGrp >> 1) & 1) * 8 + (lane & 7);
    const int bK4   = (bGrp & 1) * 8;

    if (tid < BM) { rowM[tid] = 0u; cnt[tid] = 0; }

    const int frow0 = tid >> 4;        // 0..63
    const int fc16  = tid & 15;

    auto fill_tile = [&](const __half* src, unsigned dst) {
        #pragma unroll
        for (int k = 0; k < 2; k++) {
            int r = frow0 + k * 64;
            cpasync16(dst + r * (QSTR * 2) + fc16 * 16, src + r * DIM + fc16 * 8);
        }
    };

    fill_tile(Qhb, qS);
    fill_tile(Khb,                        smemB + OFF_KHI);
    fill_tile(Khb + (size_t)BN * DIM,     smemB + OFF_KHI + TILE_B);
    cp_commit();
    fill_tile(Khb + (size_t)2 * BN * DIM, smemB + OFF_KHI + 2 * TILE_B);
    fill_tile(Khb + (size_t)3 * BN * DIM, smemB + OFF_KHI + 3 * TILE_B);
    cp_commit();

    // precomputed ldsm base addresses (add ks*32 bytes per k-step)
    const unsigned aAddr0 = qS + (unsigned)(((wm * 32 + aRow) * QSTR + aK) * 2);
    const unsigned aAddr1 = qS + (unsigned)(((wm * 32 + 16 + aRow) * QSTR + aK) * 2);
    const unsigned bOff   = (unsigned)(((wn * 16 + bRow4) * QSTR + bK4) * 2);

    // max+collect for one tile's accumulators
    auto maxcollect = [&](unsigned (&acc)[2][2][2], int nt) {
        float qm[2][2];
        #pragma unroll
        for (int m = 0; m < 2; m++) {
            #pragma unroll
            for (int h = 0; h < 2; h++) {
                __half2 x = __hmax2(*(__half2*)&acc[m][0][h], *(__half2*)&acc[m][1][h]);
                float2 f = __half22float2(x);
                float lm = fmaxf(f.x, f.y);
                lm = fmaxf(lm, __shfl_xor_sync(0xffffffffu, lm, 1));
                lm = fmaxf(lm, __shfl_xor_sync(0xffffffffu, lm, 2));
                qm[m][h] = lm;
                if ((lane & 3) == 0) {
                    const int r = wm * 32 + m * 16 + h * 8 + g;
                    if (fenc(lm) > rowM[r]) atomicMax(&rowM[r], fenc(lm));
                }
            }
        }
        __syncwarp();
        #pragma unroll
        for (int m = 0; m < 2; m++) {
            #pragma unroll
            for (int h = 0; h < 2; h++) {
                const int r = wm * 32 + m * 16 + h * 8 + g;
                const float thr = fdec(rowM[r]) - 3.5f;
                if (qm[m][h] > thr) {
                    #pragma unroll
                    for (int n = 0; n < 2; n++) {
                        float2 f = __half22float2(*(__half2*)&acc[m][n][h]);
                        #pragma unroll
                        for (int e = 0; e < 2; e++) {
                            float s = (e == 0) ? f.x : f.y;
                            if (s > thr) {
                                int p = atomicAdd(&cnt[r], 1);
                                if (p < CAP) {
                                    candS[r * CSTR + p] = s;
                                    candC[r * CSTR + p] = nt * BN + wn * 16 + n * 8 + t * 2 + e;
                                }
                            }
                        }
                    }
                }
            }
        }
    };

    for (int pp = 0; pp < PAIRS; pp++) {
        if (pp < PAIRS - 1) cp_wait<1>(); else cp_wait<0>();
        __syncthreads();                 // pair pp resident

        const int t0 = 2 * pp, t1 = 2 * pp + 1;
        const unsigned kS0 = smemB + OFF_KHI + (t0 & 3) * TILE_B + bOff;
        const unsigned kS1 = smemB + OFF_KHI + (t1 & 3) * TILE_B + bOff;

        unsigned acc0[2][2][2], acc1[2][2][2];
        #pragma unroll
        for (int m = 0; m < 2; m++)
            #pragma unroll
            for (int n = 0; n < 2; n++) {
                acc0[m][n][0] = 0u; acc0[m][n][1] = 0u;
                acc1[m][n][0] = 0u; acc1[m][n][1] = 0u;
            }

        // ks-outer: load A once, use for both tiles of the pair
        #pragma unroll
        for (int ks = 0; ks < 8; ks++) {
            unsigned a[2][4], bb0[4], bb1[4];
            ldsm4(a[0], aAddr0 + ks * 32);
            ldsm4(a[1], aAddr1 + ks * 32);
            ldsm4(bb0, kS0 + ks * 32);
            ldsm4(bb1, kS1 + ks * 32);
            #pragma unroll
            for (int m = 0; m < 2; m++) {
                mma16816h(acc0[m][0], a[m], &bb0[0]);
                mma16816h(acc0[m][1], a[m], &bb0[2]);
                mma16816h(acc1[m][0], a[m], &bb1[0]);
                mma16816h(acc1[m][1], a[m], &bb1[2]);
            }
        }

        maxcollect(acc0, t0);
        maxcollect(acc1, t1);

        __syncthreads();                 // all warps done reading pair pp
        if (pp + 2 < PAIRS) {
            const int f0 = 2 * pp + 4;
            fill_tile(Khb + (size_t)f0 * BN * DIM,       smemB + OFF_KHI + (f0 & 3) * TILE_B);
            fill_tile(Khb + (size_t)(f0 + 1) * BN * DIM, smemB + OFF_KHI + ((f0 + 1) & 3) * TILE_B);
            cp_commit();
        }
    }
    __syncthreads();

    // ---- deterministic order: per-row insertion sort by column ----
    if (tid < BM) {
        const int r = tid;
        int c_ = cnt[r]; if (c_ > CAP) { c_ = CAP; cnt[r] = CAP; }
        float* cs = candS + r * CSTR;
        int*   cc = candC + r * CSTR;
        for (int i = 1; i < c_; i++) {
            float sv = cs[i]; int kv = cc[i]; int j = i - 1;
            while (j >= 0 && cc[j] > kv) { cc[j + 1] = cc[j]; cs[j + 1] = cs[j]; j--; }
            cc[j + 1] = kv; cs[j + 1] = sv;
        }
    }
    __syncthreads();

    // ---- exact fp32 rescore: warp-per-row (4 rows/warp), 4-way batched LDG ----
    for (int r = wid; r < BM; r += 32) {
        const int c_ = cnt[r];
        float* cs = candS + r * CSTR;
        int*   cc = candC + r * CSTR;
        const float4 qv = *(const float4*)(Qb + (size_t)r * DIM + lane * 4);
        for (int j0 = 0; j0 < c_; j0 += 4) {
            float4 kv[4];
            #pragma unroll
            for (int u = 0; u < 4; u++) {
                int j = j0 + u; if (j >= c_) j = c_ - 1;
                kv[u] = *(const float4*)(Kb + (size_t)cc[j] * DIM + lane * 4);
            }
            float d[4];
            #pragma unroll
            for (int u = 0; u < 4; u++) {
                float s = fmaf(qv.x, kv[u].x, 0.f);
                s = fmaf(qv.y, kv[u].y, s);
                s = fmaf(qv.z, kv[u].z, s);
                d[u] = fmaf(qv.w, kv[u].w, s);
            }
            #pragma unroll
            for (int s = 16; s > 0; s >>= 1) {
                d[0] += __shfl_xor_sync(0xffffffffu, d[0], s);
                d[1] += __shfl_xor_sync(0xffffffffu, d[1], s);
                d[2] += __shfl_xor_sync(0xffffffffu, d[2], s);
                d[3] += __shfl_xor_sync(0xffffffffu, d[3], s);
            }
            if (lane == 0) {
                #pragma unroll
                for (int u = 0; u < 4; u++)
                    if (j0 + u < c_) cs[j0 + u] = d[u];
            }
        }
    }
    __syncthreads();

    // ---- bisection: thread-per-row, register-resident z for c_<=ZREG ----
    if (tid < BM) {
        const int r = tid;
        const int c_ = cnt[r];
        float* cs = candS + r * CSTR;
        float tau, Zv;

        if (c_ <= ZREG) {
            float z[ZREG];
            float zmax = -3.0e38f;
            #pragma unroll
            for (int j = 0; j < ZREG; j++) {
                z[j] = (j < c_) ? 0.5f * cs[j] : -3.0e38f;
                zmax = fmaxf(zmax, z[j]);
            }
            float tmin = zmax - 1.0f;
            float tmax = zmax - 0.022097086912079608f;   // float32(2048^-0.5)
            tau = 0.5f * (tmin + tmax); Zv = 0.f;
            for (int it = 0; it < NITER; it++) {
                tau = 0.5f * (tmin + tmax);
                Zv = 0.f;
                #pragma unroll
                for (int j = 0; j < ZREG; j++) {
                    float dz = fmaxf(z[j] - tau, 0.f);
                    Zv = fmaf(dz, dz, Zv);
                }
                if (Zv >= 1.0f) tmin = tau; else tmax = tau;
            }
        } else {
            float smax = -3.0e38f;
            for (int j = 0; j < c_; j++) smax = fmaxf(smax, cs[j]);
            const float zmax = 0.5f * smax;
            float tmin = zmax - 1.0f;
            float tmax = zmax - 0.022097086912079608f;
            tau = 0.5f * (tmin + tmax); Zv = 0.f;
            for (int it = 0; it < NITER; it++) {
                tau = 0.5f * (tmin + tmax);
                Zv = 0.f;
                for (int j = 0; j < c_; j++) {
                    float dz = fmaxf(0.5f * cs[j] - tau, 0.f);
                    Zv = fmaf(dz, dz, Zv);
                }
                if (Zv >= 1.0f) tmin = tau; else tmax = tau;
            }
        }
        tauA[r] = tau;
        zA[r]   = Zv;
    }
    __syncthreads();

    // ---- sparse P@V: 32 warps x 4 rows, 4-way batched V gather ----
    for (int rr = 0; rr < 4; rr++) {
        const int r = wid * 4 + rr;
        const int c_ = cnt[r];
        const float tau = tauA[r];
        const float Zv  = zA[r];
        float ax = 0.f, ay = 0.f, az = 0.f, aw = 0.f;
        for (int j0 = 0; j0 < c_; j0 += 4) {
            float4 v[4]; float w[4];
            #pragma unroll
            for (int u = 0; u < 4; u++) {
                int j = j0 + u;
                bool ok = (j < c_);
                int jc = ok ? j : (c_ - 1);
                float dz = fmaxf(0.5f * candS[r * CSTR + jc] - tau, 0.f);
                w[u] = ok ? (dz * dz) / Zv : 0.f;
                v[u] = *(const float4*)(Vb + (size_t)candC[r * CSTR + jc] * DIM + lane * 4);
            }
            #pragma unroll
            for (int u = 0; u < 4; u++) {
                ax = fmaf(w[u], v[u].x, ax);
                ay = fmaf(w[u], v[u].y, ay);
                az = fmaf(w[u], v[u].z, az);
                aw = fmaf(w[u], v[u].w, aw);
            }
        }
        *(float4*)(O + ((size_t)b * SEQ + q0 + r) * DIM + lane * 4) = make_float4(ax, ay, az, aw);
    }
}

extern "C" void kernel_launch(void* const* d_in, const int* in_sizes, int n_in,
                              void* d_out, int out_size) {
    const float* Q = (const float*)d_in[0];
    const float* K = (const float*)d_in[1];
    const float* V = (const float*)d_in[2];
    float* O = (float*)d_out;

    cvt_kernel<<<2048, 256>>>(Q, K);

    cudaFuncSetAttribute(entmax_attn_kernel,
                         cudaFuncAttributeMaxDynamicSharedMemorySize, SMEM_BYTES);
    dim3 grid(QT, BATCH);
    entmax_attn_kernel<<<grid, NTHREADS, SMEM_BYTES>>>(Q, K, V, O);
}

// round 12
// speedup vs baseline: 1.3609x; 1.0507x over previous
#include <cuda_runtime.h>
#include <cuda_fp16.h>

// SparseAttention (entmax-1.5), GB300 sm_103a. Round 11:
//  - GROUP-PRIVATE K staging: warps sharing wn (4 warps, contiguous tids) fill
//    only their 16-row slice of each K tile and sync via named barrier
//    bar.sync(wn+1, 128). ZERO block-wide barriers in the mainloop.
//  - pair processing + A-fragment reuse, 4 stages, f16-accum mma.sync.
//  - collect writes indices only (rescore regenerates scores).
//  - reg-resident bisection, 4-way batched rescore / P@V tails.

#define BATCH 8
#define SEQ   2048
#define DIM   128
#define BM    128
#define BN    128
#define NT    (SEQ / BN)       // 16
#define PAIRS (NT / 2)         // 8
#define QT    (SEQ / BM)       // 16
#define CAP   48
#define CSTR  49
#define QSTR  136              // f16 row stride (128+8 pad): 16B aligned, ldsm conflict-free
#define NITER 100
#define NTHREADS 1024
#define ZREG  12

#define TILE_B  (BM * QSTR * 2)                       // 34816
#define OFF_QHI  0
#define OFF_KHI  (OFF_QHI + TILE_B)                   // 34816
#define OFF_CS   (OFF_KHI + 4 * TILE_B)               // 174080
#define OFF_CC   (OFF_CS + BM * CSTR * 4)             // 199168
#define OFF_RM   (OFF_CC + BM * CSTR * 4)             // 224256
#define OFF_CNT  (OFF_RM + BM * 4)                    // 224768
#define OFF_TAU  (OFF_CNT + BM * 4)                   // 225280
#define OFF_Z    (OFF_TAU + BM * 4)                   // 225792
#define SMEM_BYTES (OFF_Z + BM * 4)                   // 226304

__device__ __half g_Qh[BATCH * SEQ * DIM];
__device__ __half g_Kh[BATCH * SEQ * DIM];

__global__ void cvt_kernel(const float* __restrict__ Q, const float* __restrict__ K) {
    size_t i = ((size_t)blockIdx.x * blockDim.x + threadIdx.x) * 4;
    float4 q = *(const float4*)(Q + i);
    float4 k = *(const float4*)(K + i);
    *(__half2*)(g_Qh + i)     = __floats2half2_rn(q.x, q.y);
    *(__half2*)(g_Qh + i + 2) = __floats2half2_rn(q.z, q.w);
    *(__half2*)(g_Kh + i)     = __floats2half2_rn(k.x, k.y);
    *(__half2*)(g_Kh + i + 2) = __floats2half2_rn(k.z, k.w);
}

static __device__ __forceinline__ unsigned fenc(float f) {
    unsigned u = __float_as_uint(f);
    return (u & 0x80000000u) ? ~u : (u | 0x80000000u);
}
static __device__ __forceinline__ float fdec(unsigned e) {
    return (e & 0x80000000u) ? __uint_as_float(e & 0x7fffffffu)
                             : __uint_as_float(~e);
}
static __device__ __forceinline__ void cpasync16(unsigned dst, const void* src) {
    asm volatile("cp.async.cg.shared.global [%0], [%1], 16;\n" :: "r"(dst), "l"(src));
}
static __device__ __forceinline__ void cp_commit() {
    asm volatile("cp.async.commit_group;\n");
}
template <int N>
static __device__ __forceinline__ void cp_wait() {
    asm volatile("cp.async.wait_group %0;\n" :: "n"(N));
}
static __device__ __forceinline__ void nbar(int id) {
    asm volatile("bar.sync %0, %1;" :: "r"(id), "r"(128) : "memory");
}
static __device__ __forceinline__ void ldsm4(unsigned* r, unsigned addr) {
    asm volatile("ldmatrix.sync.aligned.m8n8.x4.shared.b16 {%0,%1,%2,%3}, [%4];\n"
                 : "=r"(r[0]), "=r"(r[1]), "=r"(r[2]), "=r"(r[3])
                 : "r"(addr) : "memory");
}
static __device__ __forceinline__ void mma16816h(unsigned* c, const unsigned* a, const unsigned* b) {
    asm volatile("mma.sync.aligned.m16n8k16.row.col.f16.f16.f16.f16 "
                 "{%0,%1}, {%2,%3,%4,%5}, {%6,%7}, {%0,%1};\n"
                 : "+r"(c[0]), "+r"(c[1])
                 : "r"(a[0]), "r"(a[1]), "r"(a[2]), "r"(a[3]),
                   "r"(b[0]), "r"(b[1]));
}

__global__ __launch_bounds__(NTHREADS, 1)
void entmax_attn_kernel(const float* __restrict__ Q, const float* __restrict__ K,
                        const float* __restrict__ V, float* __restrict__ O)
{
    extern __shared__ unsigned char smem[];
    float*    candS = (float*)(smem + OFF_CS);
    int*      candC = (int*)(smem + OFF_CC);
    unsigned* rowM  = (unsigned*)(smem + OFF_RM);
    int*      cnt   = (int*)(smem + OFF_CNT);
    float*    tauA  = (float*)(smem + OFF_TAU);
    float*    zA    = (float*)(smem + OFF_Z);

    const int tid  = threadIdx.x;
    const int lane = tid & 31;
    const int wid  = tid >> 5;
    const int b    = blockIdx.y;
    const int q0   = blockIdx.x * BM;

    const float* Qb = Q + ((size_t)b * SEQ + q0) * DIM;
    const float* Kb = K + (size_t)b * SEQ * DIM;
    const float* Vb = V + (size_t)b * SEQ * DIM;
    const __half* Qhb = g_Qh + ((size_t)b * SEQ + q0) * DIM;
    const __half* Khb = g_Kh + (size_t)b * SEQ * DIM;

    const unsigned smemB = (unsigned)__cvta_generic_to_shared(smem);
    const unsigned qS = smemB + OFF_QHI;

    // 4x8 warp grid: warp tile 32(M) x 16(N); group = wn (4 warps, tids contiguous)
    const int wm = wid & 3;
    const int wn = wid >> 2;            // == tid >> 7
    const int g  = lane >> 2;
    const int t  = lane & 3;

    const int aRow = (lane & 7) + ((lane >> 3) & 1) * 8;  // ldsm x4 (A)
    const int aK   = ((lane >> 4) & 1) * 8;
    const int bGrp  = lane >> 3;                          // ldsm x4 (B): n16 x k16
    const int bRow4 = ((bGrp >> 1) & 1) * 8 + (lane & 7);
    const int bK4   = (bGrp & 1) * 8;

    if (tid < BM) { rowM[tid] = 0u; cnt[tid] = 0; }

    // ---- Q fill: all 1024 threads, 2 chunks each ----
    {
        const int fr0 = tid >> 4;          // 0..63
        const int fc  = tid & 15;
        #pragma unroll
        for (int k = 0; k < 2; k++) {
            int r = fr0 + k * 64;
            cpasync16(qS + r * (QSTR * 2) + fc * 16, Qhb + r * DIM + fc * 8);
        }
    }

    // ---- group-private slice fill: 16 rows x 16 chunks / 128 threads = 2 each ----
    const int slr = (tid & 127) >> 3;       // 0..15: local row in slice
    const int sc0 = ((tid & 127) & 7) * 2;  // chunks sc0, sc0+1
    const int srow = wn * 16 + slr;         // row within tile
    auto fill_slice = [&](int nt) {
        unsigned dst = smemB + OFF_KHI + (nt & 3) * TILE_B + srow * (QSTR * 2);
        const __half* src = Khb + (size_t)nt * BN * DIM + srow * DIM;
        cpasync16(dst + sc0 * 16,       src + sc0 * 8);
        cpasync16(dst + (sc0 + 1) * 16, src + (sc0 + 1) * 8);
    };

    fill_slice(0);
    cp_commit();                 // G0 = Q + pair0 tile0... (Q grouped with first commit)
    fill_slice(1);
    cp_commit();                 // G1
    fill_slice(2);
    fill_slice(3);
    cp_commit();                 // G2  (pair1)
    // Regroup: G(pair p) mapping -> pair0 needs G0+G1 done, pair1 needs G2.
    cp_wait<2>();                // G0 done (Q + tile0)
    __syncthreads();             // Q visible to all warps (only block barrier pre-tail)

    const unsigned aAddr0 = qS + (unsigned)(((wm * 32 + aRow) * QSTR + aK) * 2);
    const unsigned aAddr1 = qS + (unsigned)(((wm * 32 + 16 + aRow) * QSTR + aK) * 2);
    const unsigned bOff   = (unsigned)(((wn * 16 + bRow4) * QSTR + bK4) * 2);
    const int barid = wn + 1;    // named barrier ids 1..8 (0 reserved for __syncthreads)

    auto maxcollect = [&](unsigned (&acc)[2][2][2], int nt) {
        float qm[2][2];
        #pragma unroll
        for (int m = 0; m < 2; m++) {
            #pragma unroll
            for (int h = 0; h < 2; h++) {
                __half2 x = __hmax2(*(__half2*)&acc[m][0][h], *(__half2*)&acc[m][1][h]);
                float2 f = __half22float2(x);
                float lm = fmaxf(f.x, f.y);
                lm = fmaxf(lm, __shfl_xor_sync(0xffffffffu, lm, 1));
                lm = fmaxf(lm, __shfl_xor_sync(0xffffffffu, lm, 2));
                qm[m][h] = lm;
                if ((lane & 3) == 0) {
                    const int r = wm * 32 + m * 16 + h * 8 + g;
                    if (fenc(lm) > rowM[r]) atomicMax(&rowM[r], fenc(lm));
                }
            }
        }
        __syncwarp();
        #pragma unroll
        for (int m = 0; m < 2; m++) {
            #pragma unroll
            for (int h = 0; h < 2; h++) {
                const int r = wm * 32 + m * 16 + h * 8 + g;
                const float thr = fdec(rowM[r]) - 3.5f;
                if (qm[m][h] > thr) {
                    #pragma unroll
                    for (int n = 0; n < 2; n++) {
                        float2 f = __half22float2(*(__half2*)&acc[m][n][h]);
                        #pragma unroll
                        for (int e = 0; e < 2; e++) {
                            float s = (e == 0) ? f.x : f.y;
                            if (s > thr) {
                                int p = atomicAdd(&cnt[r], 1);
                                if (p < CAP) {
                                    candS[r * CSTR + p] = s;
                                    candC[r * CSTR + p] = nt * BN + wn * 16 + n * 8 + t * 2 + e;
                                }
                            }
                        }
                    }
                }
            }
        }
    };

    // commit groups so far: G0(Q+t0), G1(t1), G2(t2,t3). Loop commits G(pp+1)
    // for pair pp+2 at iteration pp. Pair pp complete when groups 0..pp+1 done
    // => outstanding <= total_committed - (pp+2).
    for (int pp = 0; pp < PAIRS; pp++) {
        // wait for pair pp: after iter pp-1, commits = 3 + max(0, min(pp, PAIRS-2) ... )
        // committed ids: G0..G(2 + #loop-commits). Loop iter j commits one group
        // (pair j+2) for j <= PAIRS-3. At iter pp, commits = 3 + min(pp, PAIRS - 2).
        // Need groups 0..(pp+1) done -> allowed outstanding = commits - (pp+2).
        {
            const int commits = 3 + (pp < PAIRS - 2 ? pp : PAIRS - 2);
            const int need    = pp + 2;
            const int out     = commits - need;
            if (out <= 0)      cp_wait<0>();
            else if (out == 1) cp_wait<1>();
            else               cp_wait<2>();
        }
        nbar(barid);             // slice visibility within group (pair pp)

        const int t0 = 2 * pp, t1 = 2 * pp + 1;
        const unsigned kS0 = smemB + OFF_KHI + (t0 & 3) * TILE_B + bOff;
        const unsigned kS1 = smemB + OFF_KHI + (t1 & 3) * TILE_B + bOff;

        unsigned acc0[2][2][2], acc1[2][2][2];
        #pragma unroll
        for (int m = 0; m < 2; m++)
            #pragma unroll
            for (int n = 0; n < 2; n++) {
                acc0[m][n][0] = 0u; acc0[m][n][1] = 0u;
                acc1[m][n][0] = 0u; acc1[m][n][1] = 0u;
            }

        #pragma unroll
        for (int ks = 0; ks < 8; ks++) {
            unsigned a[2][4], bb0[4], bb1[4];
            ldsm4(a[0], aAddr0 + ks * 32);
            ldsm4(a[1], aAddr1 + ks * 32);
            ldsm4(bb0, kS0 + ks * 32);
            ldsm4(bb1, kS1 + ks * 32);
            #pragma unroll
            for (int m = 0; m < 2; m++) {
                mma16816h(acc0[m][0], a[m], &bb0[0]);
                mma16816h(acc0[m][1], a[m], &bb0[2]);
                mma16816h(acc1[m][0], a[m], &bb1[0]);
                mma16816h(acc1[m][1], a[m], &bb1[2]);
            }
        }

        nbar(barid);             // group done reading pair pp's slices

        if (pp + 2 < PAIRS) {    // refill pair pp's stages with pair pp+2
            fill_slice(2 * pp + 4);
            fill_slice(2 * pp + 5);
            cp_commit();
        }

        maxcollect(acc0, t0);    // register/atomic work overlaps group fills
        maxcollect(acc1, t1);
    }
    __syncthreads();

    // ---- deterministic order: per-row insertion sort by column (indices only) ----
    if (tid < BM) {
        const int r = tid;
        int c_ = cnt[r]; if (c_ > CAP) { c_ = CAP; cnt[r] = CAP; }
        int* cc = candC + r * CSTR;
        for (int i = 1; i < c_; i++) {
            int kv = cc[i]; int j = i - 1;
            while (j >= 0 && cc[j] > kv) { cc[j + 1] = cc[j]; j--; }
            cc[j + 1] = kv;
        }
    }
    __syncthreads();

    // ---- exact fp32 rescore: warp-per-row (4 rows/warp), 4-way batched LDG ----
    for (int r = wid; r < BM; r += 32) {
        const int c_ = cnt[r];
        float* cs = candS + r * CSTR;
        int*   cc = candC + r * CSTR;
        const float4 qv = *(const float4*)(Qb + (size_t)r * DIM + lane * 4);
        for (int j0 = 0; j0 < c_; j0 += 4) {
            float4 kv[4];
            #pragma unroll
            for (int u = 0; u < 4; u++) {
                int j = j0 + u; if (j >= c_) j = c_ - 1;
                kv[u] = *(const float4*)(Kb + (size_t)cc[j] * DIM + lane * 4);
            }
            float d[4];
            #pragma unroll
            for (int u = 0; u < 4; u++) {
                float s = fmaf(qv.x, kv[u].x, 0.f);
                s = fmaf(qv.y, kv[u].y, s);
                s = fmaf(qv.z, kv[u].z, s);
                d[u] = fmaf(qv.w, kv[u].w, s);
            }
            #pragma unroll
            for (int s = 16; s > 0; s >>= 1) {
                d[0] += __shfl_xor_sync(0xffffffffu, d[0], s);
                d[1] += __shfl_xor_sync(0xffffffffu, d[1], s);
                d[2] += __shfl_xor_sync(0xffffffffu, d[2], s);
                d[3] += __shfl_xor_sync(0xffffffffu, d[3], s);
            }
            if (lane == 0) {
                #pragma unroll
                for (int u = 0; u < 4; u++)
                    if (j0 + u < c_) cs[j0 + u] = d[u];
            }
        }
    }
    __syncthreads();

    // ---- bisection: thread-per-row, register-resident z for c_<=ZREG ----
    if (tid < BM) {
        const int r = tid;
        const int c_ = cnt[r];
        float* cs = candS + r * CSTR;
        float tau, Zv;

        if (c_ <= ZREG) {
            float z[ZREG];
            float zmax = -3.0e38f;
            #pragma unroll
            for (int j = 0; j < ZREG; j++) {
                z[j] = (j < c_) ? 0.5f * cs[j] : -3.0e38f;
                zmax = fmaxf(zmax, z[j]);
            }
            float tmin = zmax - 1.0f;
            float tmax = zmax - 0.022097086912079608f;   // float32(2048^-0.5)
            tau = 0.5f * (tmin + tmax); Zv = 0.f;
            for (int it = 0; it < NITER; it++) {
                tau = 0.5f * (tmin + tmax);
                Zv = 0.f;
                #pragma unroll
                for (int j = 0; j < ZREG; j++) {
                    float dz = fmaxf(z[j] - tau, 0.f);
                    Zv = fmaf(dz, dz, Zv);
                }
                if (Zv >= 1.0f) tmin = tau; else tmax = tau;
            }
        } else {
            float smax = -3.0e38f;
            for (int j = 0; j < c_; j++) smax = fmaxf(smax, cs[j]);
            const float zmax = 0.5f * smax;
            float tmin = zmax - 1.0f;
            float tmax = zmax - 0.022097086912079608f;
            tau = 0.5f * (tmin + tmax); Zv = 0.f;
            for (int it = 0; it < NITER; it++) {
                tau = 0.5f * (tmin + tmax);
                Zv = 0.f;
                for (int j = 0; j < c_; j++) {
                    float dz = fmaxf(0.5f * cs[j] - tau, 0.f);
                    Zv = fmaf(dz, dz, Zv);
                }
                if (Zv >= 1.0f) tmin = tau; else tmax = tau;
            }
        }
        tauA[r] = tau;
        zA[r]   = Zv;
    }
    __syncthreads();

    // ---- sparse P@V: 32 warps x 4 rows, 4-way batched V gather ----
    for (int rr = 0; rr < 4; rr++) {
        const int r = wid * 4 + rr;
        const int c_ = cnt[r];
        const float tau = tauA[r];
        const float Zv  = zA[r];
        float ax = 0.f, ay = 0.f, az = 0.f, aw = 0.f;
        for (int j0 = 0; j0 < c_; j0 += 4) {
            float4 v[4]; float w[4];
            #pragma unroll
            for (int u = 0; u < 4; u++) {
                int j = j0 + u;
                bool ok = (j < c_);
                int jc = ok ? j : (c_ - 1);
                float dz = fmaxf(0.5f * candS[r * CSTR + jc] - tau, 0.f);
                w[u] = ok ? (dz * dz) / Zv : 0.f;
                v[u] = *(const float4*)(Vb + (size_t)candC[r * CSTR + jc] * DIM + lane * 4);
            }
            #pragma unroll
            for (int u = 0; u < 4; u++) {
                ax = fmaf(w[u], v[u].x, ax);
                ay = fmaf(w[u], v[u].y, ay);
                az = fmaf(w[u], v[u].z, az);
                aw = fmaf(w[u], v[u].w, aw);
            }
        }
        *(float4*)(O + ((size_t)b * SEQ + q0 + r) * DIM + lane * 4) = make_float4(ax, ay, az, aw);
    }
}

extern "C" void kernel_launch(void* const* d_in, const int* in_sizes, int n_in,
                              void* d_out, int out_size) {
    const float* Q = (const float*)d_in[0];
    const float* K = (const float*)d_in[1];
    const float* V = (const float*)d_in[2];
    float* O = (float*)d_out;

    cvt_kernel<<<2048, 256>>>(Q, K);

    cudaFuncSetAttribute(entmax_attn_kernel,
                         cudaFuncAttributeMaxDynamicSharedMemorySize, SMEM_BYTES);
    dim3 grid(QT, BATCH);
    entmax_attn_kernel<<<grid, NTHREADS, SMEM_BYTES>>>(Q, K, V, O);
}